// round 1
// baseline (speedup 1.0000x reference)
#include <cuda_runtime.h>
#include <math.h>

#define NCLS 80
#define MAXT 64

__constant__ float c_aw[9] = {10.f,16.f,33.f,30.f,62.f,59.f,116.f,156.f,373.f};
__constant__ float c_ah[9] = {13.f,30.f,23.f,61.f,45.f,119.f,90.f,198.f,326.f};

__device__ double g_acc;

__device__ __forceinline__ float sigf(float x) { return 1.0f / (1.0f + expf(-x)); }

__global__ void yolo_init() { g_acc = 0.0; }

__global__ void yolo_main(const float* __restrict__ p3,
                          const float* __restrict__ p4,
                          const float* __restrict__ p5,
                          const float* __restrict__ tgt,
                          int B, int T)
{
    double acc = 0.0;

    if ((int)blockIdx.x >= B) {
        // ---------------- dense: sum sigmoid(conf)^2 over all cells ----------------
        const int HW0 = 52 * 52, HW1 = 26 * 26, HW2 = 13 * 13;
        const int n0 = B * 3 * HW0;
        const int n1 = n0 + B * 3 * HW1;
        const int n2 = n1 + B * 3 * HW2;
        int nthreads = (gridDim.x - B) * blockDim.x;
        int tid0 = (blockIdx.x - B) * blockDim.x + threadIdx.x;
        for (int e = tid0; e < n2; e += nthreads) {
            const float* p; int HW, base;
            if (e < n0)      { p = p3; HW = HW0; base = e; }
            else if (e < n1) { p = p4; HW = HW1; base = e - n0; }
            else             { p = p5; HW = HW2; base = e - n1; }
            int b   = base / (3 * HW);
            int r   = base % (3 * HW);
            int a   = r / HW;
            int pos = r % HW;
            float x = p[((size_t)b * 255 + a * 85 + 4) * HW + pos];
            float s = sigf(x);
            acc += (double)(s * s);   // LAMBDA_NOOBJ = 1
        }
    } else {
        // ---------------- sparse: per-batch annotation encoding + losses ----------
        __shared__ float s_tx[MAXT], s_ty[MAXT], s_tw[MAXT], s_th[MAXT];
        __shared__ int   s_layer[MAXT], s_bl[MAXT], s_gj[MAXT], s_gi[MAXT], s_cid[MAXT];
        __shared__ int   s_do[MAXT], s_owner[MAXT];
        __shared__ int   s_nz[MAXT * 3];
        __shared__ unsigned s_cm[MAXT * 3];

        const int b = blockIdx.x;
        const int t = threadIdx.x;

        if (t < T) {
            const float* an = tgt + ((size_t)b * T + t) * 5;
            float a0 = an[0], a1 = an[1], a2 = an[2], a3 = an[3], a4 = an[4];
            bool valid = (a0 + a1 + a2 + a3 + a4) > 0.0f;
            float gwp = a2 * 416.0f, ghp = a3 * 416.0f;
            float iou[9];
            float best = -1.0f; int bn = 0;
            #pragma unroll
            for (int k = 0; k < 9; k++) {
                float inter = fminf(gwp, c_aw[k]) * fminf(ghp, c_ah[k]);
                float uni   = gwp * ghp + c_aw[k] * c_ah[k] - inter;
                float v     = inter / (uni + 1e-16f);
                iou[k] = v;
                if (v > best) { best = v; bn = k; }   // first max wins (jnp.argmax)
            }
            int layer = bn / 3;
            int W = (layer == 0) ? 52 : ((layer == 1) ? 26 : 13);
            float Wf = (float)W;
            float gx = a0 * Wf, gy = a1 * Wf;
            int gi = min(max((int)gx, 0), W - 1);
            int gj = min(max((int)gy, 0), W - 1);
            float scale = Wf / 416.0f;
            float saw = c_aw[bn] * scale, sah = c_ah[bn] * scale;
            s_tx[t] = gx - (float)gi;
            s_ty[t] = gy - (float)gj;
            s_tw[t] = (a2 * Wf) / saw;
            s_th[t] = (a3 * Wf) / sah;
            s_layer[t] = layer;
            s_bl[t] = bn - 3 * layer;
            s_gj[t] = gj; s_gi[t] = gi;
            s_cid[t] = min(max((int)a4, 0), NCLS - 1);
            s_do[t] = valid ? 1 : 0;
            #pragma unroll
            for (int a = 0; a < 3; a++)
                s_nz[t * 3 + a] = (iou[3 * layer + a] > 0.5f) ? 1 : 0;
        }
        __syncthreads();

        // noobj zeroed-cell subtraction (dedup by first occurrence of (layer,a,gj,gi))
        for (int idx = threadIdx.x; idx < T * 3; idx += blockDim.x) {
            int ti = idx / 3, a = idx % 3;
            if (!s_do[ti] || !s_nz[idx]) continue;
            bool first = true;
            for (int u = 0; u < ti; u++) {
                if (s_do[u] && s_nz[u * 3 + a] &&
                    s_layer[u] == s_layer[ti] && s_gj[u] == s_gj[ti] && s_gi[u] == s_gi[ti]) {
                    first = false; break;
                }
            }
            if (first) {
                int L = s_layer[ti];
                int W = (L == 0) ? 52 : ((L == 1) ? 26 : 13);
                int HW = W * W;
                const float* p = (L == 0) ? p3 : ((L == 1) ? p4 : p5);
                int pos = s_gj[ti] * W + s_gi[ti];
                float x = p[((size_t)b * 255 + a * 85 + 4) * HW + pos];
                float s = sigf(x);
                acc -= (double)(s * s);
            }
        }

        // owner resolution + class union mask + box/obj loss
        if (t < T) {
            s_owner[t] = 0;
            if (s_do[t]) {
                bool owner = true;
                for (int u = t + 1; u < T; u++) {
                    if (s_do[u] && s_layer[u] == s_layer[t] && s_bl[u] == s_bl[t] &&
                        s_gj[u] == s_gj[t] && s_gi[u] == s_gi[t]) { owner = false; break; }
                }
                s_owner[t] = owner ? 1 : 0;
                if (owner) {
                    unsigned m0 = 0, m1 = 0, m2 = 0;
                    for (int u = 0; u < T; u++) {
                        if (s_do[u] && s_layer[u] == s_layer[t] && s_bl[u] == s_bl[t] &&
                            s_gj[u] == s_gj[t] && s_gi[u] == s_gi[t]) {
                            int c = s_cid[u];
                            if (c < 32) m0 |= 1u << c;
                            else if (c < 64) m1 |= 1u << (c - 32);
                            else m2 |= 1u << (c - 64);
                        }
                    }
                    s_cm[t * 3 + 0] = m0; s_cm[t * 3 + 1] = m1; s_cm[t * 3 + 2] = m2;

                    int L = s_layer[t];
                    int W = (L == 0) ? 52 : ((L == 1) ? 26 : 13);
                    int HW = W * W;
                    const float* p = (L == 0) ? p3 : ((L == 1) ? p4 : p5);
                    size_t base = ((size_t)b * 255 + s_bl[t] * 85) * HW + (s_gj[t] * W + s_gi[t]);
                    float px = sigf(p[base]);
                    float py = sigf(p[base + HW]);
                    float pw = expf(p[base + 2 * (size_t)HW]);
                    float ph = expf(p[base + 3 * (size_t)HW]);
                    float pc = sigf(p[base + 4 * (size_t)HW]);
                    float dx = px - s_tx[t], dy = py - s_ty[t];
                    float dw = pw - s_tw[t], dh = ph - s_th[t];
                    acc += (double)(dx * dx + dy * dy + dw * dw + dh * dh); // LAMBDA_COORD=1
                    float dc = pc - 1.0f;
                    acc += 5.0 * (double)(dc * dc);                          // LAMBDA_OBJ=5
                }
            }
        }
        __syncthreads();

        // class BCE at owner cells (LAMBDA_CLASS = 1)
        for (int idx = threadIdx.x; idx < T * NCLS; idx += blockDim.x) {
            int ti = idx / NCLS, c = idx % NCLS;
            if (!s_owner[ti]) continue;
            int L = s_layer[ti];
            int W = (L == 0) ? 52 : ((L == 1) ? 26 : 13);
            int HW = W * W;
            const float* p = (L == 0) ? p3 : ((L == 1) ? p4 : p5);
            float x = p[((size_t)b * 255 + s_bl[ti] * 85 + 5 + c) * HW +
                        (s_gj[ti] * W + s_gi[ti])];
            float pc = sigf(x);
            unsigned w = s_cm[ti * 3 + (c >> 5)];
            bool tc = (w >> (c & 31)) & 1u;
            float l;
            if (tc) l = -fmaxf(logf(pc), -100.0f);
            else    l = -fmaxf(log1pf(-pc), -100.0f);
            acc += (double)l;
        }
    }

    // block reduce (blockDim.x == 256) + global atomic
    __shared__ double sred[256];
    sred[threadIdx.x] = acc;
    __syncthreads();
    for (int s = 128; s > 0; s >>= 1) {
        if ((int)threadIdx.x < s) sred[threadIdx.x] += sred[threadIdx.x + s];
        __syncthreads();
    }
    if (threadIdx.x == 0 && sred[0] != 0.0) atomicAdd(&g_acc, sred[0]);
}

__global__ void yolo_final(float* out, int B) {
    out[0] = (float)(g_acc / (double)B);
}

extern "C" void kernel_launch(void* const* d_in, const int* in_sizes, int n_in,
                              void* d_out, int out_size)
{
    const float* p3  = (const float*)d_in[0];
    const float* p4  = (const float*)d_in[1];
    const float* p5  = (const float*)d_in[2];
    const float* tgt = (const float*)d_in[3];

    int B = in_sizes[0] / (255 * 52 * 52);
    int T = in_sizes[3] / (B * 5);
    if (T > MAXT) T = MAXT;

    yolo_init<<<1, 1>>>();
    int denseBlocks = 224;
    yolo_main<<<B + denseBlocks, 256>>>(p3, p4, p5, tgt, B, T);
    yolo_final<<<1, 1>>>((float*)d_out, B);
}